// round 5
// baseline (speedup 1.0000x reference)
#include <cuda_runtime.h>

// NEAT feed-forward DAG evaluator — R4: k-pair packed FFMA2 (fma.rn.f32x2).
// x[4096,512] f32, W[1536,2048] f32 strictly lower-tri, b[1536], out[4096,256].
//
// Per CTA: BR=16 batch rows, full 2048-wide activation tile in SMEM.
// Per chunk of CC=64 nodes:
//   phase 1: panel GEMM Z[16,64] += Out[16,0:g0] @ W_chunk^T
//       512 threads = 8 k-splits x (4 rows x 4 cols). W staged as k-PAIR
//       float2s: wS2[kpair][col]; A k-pairs come free from contiguous f32x2
//       halves of a 16B load. All FMAs are packed fma.rn.f32x2 -> half the
//       FFMA-pipe work of R3. wS2 is double-buffered: ONE barrier per block.
//   phase 2: 64-node triangle, one warp per batch row (unchanged from R3).

#define NTHREADS 512
#define BR 16
#define CC 64
#define NIN 512
#define NEVAL 1536
#define NN 2048
#define NOUT 256
#define NCHUNK (NEVAL / CC)      // 24
#define SO 2052                  // outS row stride (floats)
#define WS2R 66                  // wS2 row stride (float2 units) - keeps 16B align
#define WS2SZ (32 * WS2R)        // one wS2 buffer (float2 units)
#define WDR 68                   // wDT row stride (floats)
#define ZR 66                    // zS/zR row stride (floats)

#define SMEM_FLOATS (BR*SO + 2*WS2SZ*2 + CC*WDR + 8*BR*ZR + BR*ZR)
#define SMEM_BYTES (SMEM_FLOATS * 4)

typedef unsigned long long ull;

__device__ __forceinline__ void ffma2(ull& d, ull a, ull b) {
    asm("fma.rn.f32x2 %0, %1, %2, %0;" : "+l"(d) : "l"(a), "l"(b));
}
__device__ __forceinline__ float pairsum(ull v) {
    return __uint_as_float((unsigned)v) + __uint_as_float((unsigned)(v >> 32));
}

__global__ void __launch_bounds__(NTHREADS, 1)
neat_ff_kernel(const float* __restrict__ x,
               const float* __restrict__ W,
               const float* __restrict__ bias,
               float* __restrict__ out)
{
    extern __shared__ float smem[];
    float*  outS = smem;                       // [BR][SO]
    float2* wS2  = (float2*)(outS + BR * SO);  // 2 x [32 kpair][WS2R] float2
    float*  wDT  = (float*)(wS2 + 2 * WS2SZ);  // [CC j][WDR] transposed diag blk
    float*  zS   = wDT + CC * WDR;             // [8 sp][BR][ZR]
    float*  zR   = zS + 8 * BR * ZR;           // [BR][ZR]

    const int tid  = threadIdx.x;
    const int row0 = blockIdx.x * BR;

    // ---- load x tile (float4, coalesced) ----
    for (int i = tid; i < BR * (NIN / 4); i += NTHREADS) {
        int r = i >> 7, q = i & 127;
        *(float4*)&outS[r * SO + 4 * q] = *(const float4*)&x[(row0 + r) * NIN + 4 * q];
    }

    // GEMM mapping: sp = k-split (8 k each), rows r0..r0+3, cols {2cg,2cg+1,32+2cg,32+2cg+1}
    const int sp = tid >> 6;                       // 0..7 (uniform per warp)
    const int r0 = 8 * ((tid >> 5) & 1) + 4 * ((tid >> 4) & 1);
    const int cg = tid & 15;

    // staging mapping (coalesced LDG): node ssc, k-quad ssq0 (+8 for v1)
    const int ssc  = (tid >> 3) & 63;
    const int ssq0 = tid & 7;

    const int lane = tid & 31;
    const int wrp  = tid >> 5;                     // triangle: warp -> batch row

    // prefetch first W block (chunk 0, kb 0)
    float4 v0 = *(const float4*)&W[ssc * NN + 4 * ssq0];
    float4 v1 = *(const float4*)&W[ssc * NN + 4 * (ssq0 + 8)];

    int buf = 0;

    for (int ch = 0; ch < NCHUNK; ch++) {
        const int i0 = ch * CC;
        const int g0 = NIN + i0;

        ull acc[4][4];
        #pragma unroll
        for (int r = 0; r < 4; r++)
            #pragma unroll
            for (int c = 0; c < 4; c++) acc[r][c] = 0ull;

        // ---- phase 1: panel GEMM, ONE barrier per 64-k block ----
        for (int kb = 0; kb < g0; kb += CC) {
            // commit prefetched block -> wS2[buf] as k-pairs
            {
                float2* b = wS2 + buf * WS2SZ;
                b[(2 * ssq0     ) * WS2R + ssc] = make_float2(v0.x, v0.y);
                b[(2 * ssq0 +  1) * WS2R + ssc] = make_float2(v0.z, v0.w);
                b[(2 * ssq0 + 16) * WS2R + ssc] = make_float2(v1.x, v1.y);
                b[(2 * ssq0 + 17) * WS2R + ssc] = make_float2(v1.z, v1.w);
            }
            __syncthreads();
            // prefetch next block (diagonal block when nkb == g0)
            {
                int nkb = kb + CC;
                v0 = *(const float4*)&W[(i0 + ssc) * NN + nkb + 4 * ssq0];
                v1 = *(const float4*)&W[(i0 + ssc) * NN + nkb + 4 * (ssq0 + 8)];
            }
            // packed micro-kernel: 2 quads of 4 k
            const float2* wb = wS2 + buf * WS2SZ;
            #pragma unroll
            for (int q = 0; q < 2; q++) {
                const int kpa = 4 * sp + 2 * q;
                const int k0  = 8 * sp + 4 * q;
                ulonglong2 wA = *(const ulonglong2*)(wb +  kpa      * WS2R      + 2 * cg);
                ulonglong2 wB = *(const ulonglong2*)(wb +  kpa      * WS2R + 32 + 2 * cg);
                ulonglong2 wC = *(const ulonglong2*)(wb + (kpa + 1) * WS2R      + 2 * cg);
                ulonglong2 wD = *(const ulonglong2*)(wb + (kpa + 1) * WS2R + 32 + 2 * cg);
                #pragma unroll
                for (int r = 0; r < 4; r++) {
                    ulonglong2 a = *(const ulonglong2*)&outS[(r0 + r) * SO + kb + k0];
                    ffma2(acc[r][0], a.x, wA.x);
                    ffma2(acc[r][1], a.x, wA.y);
                    ffma2(acc[r][2], a.x, wB.x);
                    ffma2(acc[r][3], a.x, wB.y);
                    ffma2(acc[r][0], a.y, wC.x);
                    ffma2(acc[r][1], a.y, wC.y);
                    ffma2(acc[r][2], a.y, wD.x);
                    ffma2(acc[r][3], a.y, wD.y);
                }
            }
            buf ^= 1;
        }

        // ---- chunk epilogue: partials -> zS, diag -> wDT, prefetch next ----
        #pragma unroll
        for (int r = 0; r < 4; r++) {
            int zb = (sp * BR + r0 + r) * ZR;
            *(float2*)&zS[zb + 2 * cg] =
                make_float2(pairsum(acc[r][0]), pairsum(acc[r][1]));
            *(float2*)&zS[zb + 32 + 2 * cg] =
                make_float2(pairsum(acc[r][2]), pairsum(acc[r][3]));
        }
        {   // diagonal block (in v) -> wDT transposed: wDT[j][node]
            int j0 = 4 * ssq0;
            wDT[(j0 + 0) * WDR + ssc] = v0.x;
            wDT[(j0 + 1) * WDR + ssc] = v0.y;
            wDT[(j0 + 2) * WDR + ssc] = v0.z;
            wDT[(j0 + 3) * WDR + ssc] = v0.w;
            int j1 = j0 + 32;
            wDT[(j1 + 0) * WDR + ssc] = v1.x;
            wDT[(j1 + 1) * WDR + ssc] = v1.y;
            wDT[(j1 + 2) * WDR + ssc] = v1.z;
            wDT[(j1 + 3) * WDR + ssc] = v1.w;
        }
        if (ch + 1 < NCHUNK) {   // prefetch first block of next chunk
            v0 = *(const float4*)&W[(i0 + CC + ssc) * NN + 4 * ssq0];
            v1 = *(const float4*)&W[(i0 + CC + ssc) * NN + 4 * (ssq0 + 8)];
        }
        __syncthreads();                   // zS, wDT visible
        // reduce 8 split-K partials -> zR
        #pragma unroll
        for (int t = 0; t < 2; t++) {
            int idx = tid + t * NTHREADS;
            int k = idx & 63, r = idx >> 6;
            float s = zS[(r) * ZR + k];
            #pragma unroll
            for (int s8 = 1; s8 < 8; s8++)
                s += zS[(s8 * BR + r) * ZR + k];
            zR[r * ZR + k] = s;
        }
        __syncthreads();                   // zR visible

        // ---- phase 2: triangle, one warp per batch row, no block syncs ----
        {
            const int r  = wrp;
            const int k0 = lane, k1 = lane + 32;
            float a0t = __ldg(&bias[i0 + k0]) + zR[r * ZR + k0];
            float a1t = __ldg(&bias[i0 + k1]) + zR[r * ZR + k1];
            float o0 = 0.f, o1 = 0.f;
            #pragma unroll 4
            for (int j = 0; j < CC; j++) {
                float w0 = wDT[j * WDR + k0];
                float w1 = wDT[j * WDR + k1];
                float zj = __shfl_sync(0xffffffffu, (j < 32) ? a0t : a1t, j & 31);
                float t5 = fminf(fmaxf(5.0f * zj, -60.0f), 60.0f);
                float o  = __fdividef(1.0f, 1.0f + __expf(-t5));
                if (j == k0) o0 = o;
                if (j == k1) o1 = o;
                if (k0 > j) a0t = fmaf(w0, o, a0t);
                if (k1 > j) a1t = fmaf(w1, o, a1t);
            }
            outS[r * SO + g0 + k0] = o0;
            outS[r * SO + g0 + k1] = o1;
        }
        // next chunk's first __syncthreads orders new activations vs readers
    }

    __syncthreads();
    // ---- write output: last NOUT columns ----
    for (int i = tid; i < BR * (NOUT / 4); i += NTHREADS) {
        int r = i >> 6, q = i & 63;
        *(float4*)&out[(row0 + r) * NOUT + 4 * q] =
            *(const float4*)&outS[r * SO + (NN - NOUT) + 4 * q];
    }
}

extern "C" void kernel_launch(void* const* d_in, const int* in_sizes, int n_in,
                              void* d_out, int out_size) {
    const float* x    = (const float*)d_in[0];
    const float* W    = (const float*)d_in[1];
    const float* bias = (const float*)d_in[2];
    float* out        = (float*)d_out;
    (void)in_sizes; (void)n_in; (void)out_size;

    cudaFuncSetAttribute(neat_ff_kernel,
                         cudaFuncAttributeMaxDynamicSharedMemorySize,
                         SMEM_BYTES);
    neat_ff_kernel<<<4096 / BR, NTHREADS, SMEM_BYTES>>>(x, W, bias, out);
}